// round 1
// baseline (speedup 1.0000x reference)
#include <cuda_runtime.h>
#include <math_constants.h>

// Problem constants
#define Nn 8
#define Cc 32
#define Hh 112
#define Ww 112
#define Oo 32
#define KK 3

#define TILE 8            // 8x8 spatial tile per CTA
#define THREADS 128
#define PATCH_R (TILE + 2)   // 10
#define PITCH 12             // padded row pitch (floats) -> 48B, keeps float4 loads aligned
#define SX_FLOATS (Cc * PATCH_R * PITCH)   // 3840 floats = 15360 B (static smem, < 48KB)

#define NTW (Ww / TILE)   // 14
#define NTH (Hh / TILE)   // 14
#define NTILES (Nn * NTH * NTW)   // 1568

// Transposed weights: wT[(c*9 + kh*3 + kw) * 32 + o]  -> 4 consecutive o = one LDG.128
__device__ __align__(16) float g_wT[Cc * 9 * Oo];

__global__ void transpose_w_kernel(const float* __restrict__ w) {
    int idx = blockIdx.x * blockDim.x + threadIdx.x;
    if (idx < Oo * Cc * 9) {
        int o = idx / (Cc * 9);       // global layout: [o][c][kh][kw]
        int r = idx - o * (Cc * 9);   // r = c*9 + kh*3 + kw
        g_wT[r * Oo + o] = w[idx];
    }
}

__global__ void __launch_bounds__(THREADS, 12)
semiconv_kernel(const float* __restrict__ x, float* __restrict__ out) {
    __shared__ float sx[SX_FLOATS];   // [c][patch_row][PITCH]

    const int tid  = threadIdx.x;
    const int tile = blockIdx.x;

    const int tw  = tile % NTW;
    const int th  = (tile / NTW) % NTH;
    const int n   = tile / (NTW * NTH);
    const int gi0 = th * TILE;
    const int gj0 = tw * TILE;

    // ---- load x patch (with -inf halo) into smem ----
    const float* xn = x + (size_t)n * Cc * Hh * Ww;
    #pragma unroll 1
    for (int idx = tid; idx < Cc * PATCH_R * PATCH_R; idx += THREADS) {
        int c   = idx / (PATCH_R * PATCH_R);
        int rem = idx - c * (PATCH_R * PATCH_R);
        int rr  = rem / PATCH_R;
        int cc  = rem - rr * PATCH_R;
        int gi  = gi0 + rr - 1;
        int gj  = gj0 + cc - 1;
        float v = -CUDART_INF_F;
        if ((unsigned)gi < (unsigned)Hh && (unsigned)gj < (unsigned)Ww)
            v = xn[(c * Hh + gi) * Ww + gj];
        sx[(c * PATCH_R + rr) * PITCH + cc] = v;
    }
    __syncthreads();

    // ---- register tile: 4 o  x  4 consecutive pixels (one row) ----
    const int og   = tid & 7;         // o group: o0 = og*4  (8 groups cover 32 o)
    const int pg   = tid >> 3;        // 16 pixel groups: 8 rows x 2 col-groups
    const int prow = pg >> 1;
    const int pj   = (pg & 1) * 4;

    float acc[4][4];
    #pragma unroll
    for (int a = 0; a < 4; ++a)
        #pragma unroll
        for (int b = 0; b < 4; ++b)
            acc[a][b] = -CUDART_INF_F;

    const float* xc = &sx[prow * PITCH + pj];
    const float* wc = &g_wT[og * 4];

    #pragma unroll 1
    for (int c = 0; c < Cc; ++c) {
        #pragma unroll
        for (int kh = 0; kh < KK; ++kh) {
            // 6 x-values cover kw 0..2 for 4 pixels; aligned float4 + float2
            float4 xa = *reinterpret_cast<const float4*>(xc + kh * PITCH);
            float2 xb = *reinterpret_cast<const float2*>(xc + kh * PITCH + 4);
            float xv[6] = {xa.x, xa.y, xa.z, xa.w, xb.x, xb.y};
            #pragma unroll
            for (int kw = 0; kw < KK; ++kw) {
                float4 w4 = *reinterpret_cast<const float4*>(wc + (kh * KK + kw) * Oo);
                float wv[4] = {w4.x, w4.y, w4.z, w4.w};
                #pragma unroll
                for (int oo = 0; oo < 4; ++oo)
                    #pragma unroll
                    for (int pp = 0; pp < 4; ++pp)
                        acc[oo][pp] = fmaxf(acc[oo][pp], fminf(xv[kw + pp], wv[oo]));
            }
        }
        xc += PATCH_R * PITCH;
        wc += 9 * Oo;
    }

    // ---- write: 4 o x one float4 row each ----
    const int i = gi0 + prow;
    const int j = gj0 + pj;
    float* op = out + (((size_t)n * Oo + og * 4) * Hh + i) * Ww + j;
    #pragma unroll
    for (int oo = 0; oo < 4; ++oo) {
        float4 v = make_float4(acc[oo][0], acc[oo][1], acc[oo][2], acc[oo][3]);
        *reinterpret_cast<float4*>(op) = v;
        op += (size_t)Hh * Ww;
    }
}

extern "C" void kernel_launch(void* const* d_in, const int* in_sizes, int n_in,
                              void* d_out, int out_size) {
    const float* x = (const float*)d_in[0];       // (8, 32, 112, 112) fp32
    const float* w = (const float*)d_in[1];       // (32, 32, 3, 3) fp32
    float* out = (float*)d_out;                   // (8, 32, 112, 112) fp32

    transpose_w_kernel<<<(Oo * Cc * 9 + 255) / 256, 256>>>(w);
    semiconv_kernel<<<NTILES, THREADS>>>(x, out);
}

// round 2
// speedup vs baseline: 1.9113x; 1.9113x over previous
#include <cuda_runtime.h>
#include <cuda_fp16.h>
#include <math_constants.h>

// Problem constants
#define Nn 8
#define Cc 32
#define C2 (Cc / 2)       // 16 channel-pairs
#define Hh 112
#define Ww 112
#define Oo 32
#define KK 3

#define TILE 8            // 8x8 spatial tile per CTA
#define THREADS 128
#define PATCH_R (TILE + 2)   // 10
#define PITCH 12             // row pitch in half2 elements (48B) -> keeps 16B vector loads aligned
#define SX_ELEMS (C2 * PATCH_R * PITCH)   // 1920 half2 = 7680 B

#define NTW (Ww / TILE)   // 14
#define NTH (Hh / TILE)   // 14
#define NTILES (Nn * NTH * NTW)   // 1568

// Pair-transposed weights: g_wT2[(c2*9 + kh*3 + kw) * 32 + o] = half2(w[o][2c2][k], w[o][2c2+1][k])
// 4 consecutive o = one 16B load.
__device__ __align__(16) __half2 g_wT2[C2 * 9 * Oo];

__global__ void prep_w_kernel(const float* __restrict__ w) {
    int idx = blockIdx.x * blockDim.x + threadIdx.x;   // over o * c2 * 9
    if (idx < Oo * C2 * 9) {
        int o  = idx / (C2 * 9);
        int r  = idx - o * (C2 * 9);     // r = c2*9 + kh*3 + kw
        int c2 = r / 9;
        int k  = r - c2 * 9;             // kh*3+kw
        // global w layout: [o][c][kh][kw]
        float w0 = w[(o * Cc + 2 * c2) * 9 + k];
        float w1 = w[(o * Cc + 2 * c2 + 1) * 9 + k];
        g_wT2[r * Oo + o] = __floats2half2_rn(w0, w1);
    }
}

__global__ void __launch_bounds__(THREADS, 12)
semiconv_kernel(const float* __restrict__ x, float* __restrict__ out) {
    __shared__ __align__(16) __half2 sx2[SX_ELEMS];   // [c2][patch_row][PITCH]

    const int tid  = threadIdx.x;
    const int tile = blockIdx.x;

    const int tw  = tile % NTW;
    const int th  = (tile / NTW) % NTH;
    const int n   = tile / (NTW * NTH);
    const int gi0 = th * TILE;
    const int gj0 = tw * TILE;

    // ---- load x patch (with -inf halo), pack channel pairs into half2 ----
    const float* xn = x + (size_t)n * Cc * Hh * Ww;
    #pragma unroll 1
    for (int idx = tid; idx < C2 * PATCH_R * PATCH_R; idx += THREADS) {
        int c2  = idx / (PATCH_R * PATCH_R);
        int rem = idx - c2 * (PATCH_R * PATCH_R);
        int rr  = rem / PATCH_R;
        int cc  = rem - rr * PATCH_R;
        int gi  = gi0 + rr - 1;
        int gj  = gj0 + cc - 1;
        float v0 = -CUDART_INF_F, v1 = -CUDART_INF_F;
        if ((unsigned)gi < (unsigned)Hh && (unsigned)gj < (unsigned)Ww) {
            const float* p = xn + ((2 * c2) * Hh + gi) * Ww + gj;
            v0 = p[0];
            v1 = p[Hh * Ww];
        }
        sx2[(c2 * PATCH_R + rr) * PITCH + cc] = __floats2half2_rn(v0, v1);
    }
    __syncthreads();

    // ---- register tile: 4 o  x  4 consecutive pixels (one row) ----
    const int og   = tid & 7;         // o group: o0 = og*4
    const int pg   = tid >> 3;        // 16 pixel groups: 8 rows x 2 col-groups
    const int prow = pg >> 1;
    const int pj   = (pg & 1) * 4;

    const __half2 NEGINF2 = __halves2half2(__ushort_as_half(0xFC00), __ushort_as_half(0xFC00));

    __half2 acc[4][4];
    #pragma unroll
    for (int a = 0; a < 4; ++a)
        #pragma unroll
        for (int b = 0; b < 4; ++b)
            acc[a][b] = NEGINF2;

    const __half2* xc = &sx2[prow * PITCH + pj];
    const __half2* wc = &g_wT2[og * 4];

    #pragma unroll 1
    for (int c2 = 0; c2 < C2; ++c2) {
        #pragma unroll
        for (int kh = 0; kh < KK; ++kh) {
            // 6 half2 cover kw 0..2 for 4 pixels: 16B + 8B aligned loads
            uint4 ra = *reinterpret_cast<const uint4*>(xc + kh * PITCH);
            uint2 rb = *reinterpret_cast<const uint2*>(xc + kh * PITCH + 4);
            __half2 xv[6];
            xv[0] = *reinterpret_cast<__half2*>(&ra.x);
            xv[1] = *reinterpret_cast<__half2*>(&ra.y);
            xv[2] = *reinterpret_cast<__half2*>(&ra.z);
            xv[3] = *reinterpret_cast<__half2*>(&ra.w);
            xv[4] = *reinterpret_cast<__half2*>(&rb.x);
            xv[5] = *reinterpret_cast<__half2*>(&rb.y);
            #pragma unroll
            for (int kw = 0; kw < KK; ++kw) {
                uint4 rw = *reinterpret_cast<const uint4*>(wc + (kh * KK + kw) * Oo);
                __half2 wv[4];
                wv[0] = *reinterpret_cast<__half2*>(&rw.x);
                wv[1] = *reinterpret_cast<__half2*>(&rw.y);
                wv[2] = *reinterpret_cast<__half2*>(&rw.z);
                wv[3] = *reinterpret_cast<__half2*>(&rw.w);
                #pragma unroll
                for (int oo = 0; oo < 4; ++oo)
                    #pragma unroll
                    for (int pp = 0; pp < 4; ++pp)
                        acc[oo][pp] = __hmax2(acc[oo][pp], __hmin2(xv[kw + pp], wv[oo]));
            }
        }
        xc += PATCH_R * PITCH;
        wc += 9 * Oo;
    }

    // ---- reduce halves, write: 4 o x one float4 row each ----
    const int i = gi0 + prow;
    const int j = gj0 + pj;
    float* op = out + (((size_t)n * Oo + og * 4) * Hh + i) * Ww + j;
    #pragma unroll
    for (int oo = 0; oo < 4; ++oo) {
        float4 v;
        v.x = __half2float(__hmax(__low2half(acc[oo][0]), __high2half(acc[oo][0])));
        v.y = __half2float(__hmax(__low2half(acc[oo][1]), __high2half(acc[oo][1])));
        v.z = __half2float(__hmax(__low2half(acc[oo][2]), __high2half(acc[oo][2])));
        v.w = __half2float(__hmax(__low2half(acc[oo][3]), __high2half(acc[oo][3])));
        *reinterpret_cast<float4*>(op) = v;
        op += (size_t)Hh * Ww;
    }
}

extern "C" void kernel_launch(void* const* d_in, const int* in_sizes, int n_in,
                              void* d_out, int out_size) {
    const float* x = (const float*)d_in[0];       // (8, 32, 112, 112) fp32
    const float* w = (const float*)d_in[1];       // (32, 32, 3, 3) fp32
    float* out = (float*)d_out;                   // (8, 32, 112, 112) fp32

    prep_w_kernel<<<(Oo * C2 * 9 + 255) / 256, 256>>>(w);
    semiconv_kernel<<<NTILES, THREADS>>>(x, out);
}